// round 1
// baseline (speedup 1.0000x reference)
#include <cuda_runtime.h>
#include <cuda_bf16.h>
#include <math.h>

// Problem constants (validated against in_sizes at launch)
#define MAXN 100000
#define D_IN 128
#define D_HID 64
#define D_OUT 40

// ---------------- scratch (static device allocations) ----------------
__device__ float g_h  [MAXN * 64];   // GEMM output (stride 64)
__device__ float g_agg[MAXN * 64];   // scatter accumulator
__device__ float g_x  [MAXN * 64];   // layer activation
__device__ float g_deg [MAXN];
__device__ float g_dinv[MAXN];
__device__ float g_W3p[64 * 64];     // W3 padded 40->64 cols
__device__ int   g_is64;

// ---------------- edge-index dtype detection ----------------
// If edge_index is int64 (little-endian), the high 32-bit word of every entry
// is 0 (node ids < 2^17). If int32, odd words are random values in [0,1e5).
__global__ void detect_kernel(const unsigned* __restrict__ w) {
    int nz = 0;
    for (int i = threadIdx.x; i < 4096; i += 32)
        if (w[2 * i + 1] != 0u) nz = 1;
    unsigned m = __ballot_sync(0xffffffffu, nz);
    if (threadIdx.x == 0) g_is64 = (m == 0u) ? 1 : 0;
}

__device__ __forceinline__ int load_idx(const void* p, long long e, int is64) {
    return is64 ? (int)((const long long*)p)[e] : ((const int*)p)[e];
}

// ---------------- utility kernels ----------------
__global__ void zero_kernel(float4* __restrict__ p, int n4) {
    int i = blockIdx.x * blockDim.x + threadIdx.x;
    int stride = gridDim.x * blockDim.x;
    float4 z = make_float4(0.f, 0.f, 0.f, 0.f);
    for (; i < n4; i += stride) p[i] = z;
}

__global__ void deg_kernel(const void* __restrict__ eidx, float* __restrict__ deg, int E) {
    int e = blockIdx.x * blockDim.x + threadIdx.x;
    if (e >= E) return;
    int is64 = g_is64;
    int d = load_idx(eidx, (long long)E + e, is64);
    atomicAdd(&deg[d], 1.0f);
}

__global__ void dinv_kernel(const float* __restrict__ deg, float* __restrict__ dinv, int N) {
    int i = blockIdx.x * blockDim.x + threadIdx.x;
    if (i < N) dinv[i] = rsqrtf(deg[i] + 1.0f);
}

__global__ void padW3_kernel(const float* __restrict__ W3, float* __restrict__ Wp) {
    int i = blockIdx.x * blockDim.x + threadIdx.x;
    if (i < 64 * 64) {
        int r = i / 64, c = i % 64;
        Wp[i] = (c < D_OUT) ? W3[r * D_OUT + c] : 0.0f;
    }
}

// ---------------- tiled GEMM: H[N,64] = X[N,DIN] @ W[DIN,64] ----------------
// 256 threads, block tile 64 nodes x 64 cols, each thread 4x4 register tile.
template <int DIN>
__global__ void gemm_kernel(const float* __restrict__ X, const float* __restrict__ W,
                            float* __restrict__ H, int N) {
    constexpr int BN = 64;
    constexpr int KC = 32;
    __shared__ float Xs[BN][KC + 1];
    __shared__ float Ws[KC][64];
    const int tx = threadIdx.x % 16;   // col group -> cols 4*tx..4*tx+3
    const int ty = threadIdx.x / 16;   // node group -> nodes 4*ty..4*ty+3
    const int n0 = blockIdx.x * BN;

    float acc[4][4] = {};

    for (int k0 = 0; k0 < DIN; k0 += KC) {
        // load X tile (BN x KC), float4-vectorized, OOB rows -> 0
        for (int i = threadIdx.x; i < BN * (KC / 4); i += 256) {
            int row = i / (KC / 4);
            int c4  = i % (KC / 4);
            int n = n0 + row;
            float4 v = make_float4(0.f, 0.f, 0.f, 0.f);
            if (n < N) v = *(const float4*)(X + (size_t)n * DIN + k0 + c4 * 4);
            Xs[row][c4 * 4 + 0] = v.x;
            Xs[row][c4 * 4 + 1] = v.y;
            Xs[row][c4 * 4 + 2] = v.z;
            Xs[row][c4 * 4 + 3] = v.w;
        }
        // load W tile (KC x 64)
        for (int i = threadIdx.x; i < KC * (64 / 4); i += 256) {
            int r  = i / 16;
            int c4 = i % 16;
            *(float4*)&Ws[r][c4 * 4] = *(const float4*)(W + (size_t)(k0 + r) * 64 + c4 * 4);
        }
        __syncthreads();
        #pragma unroll
        for (int k = 0; k < KC; k++) {
            float4 wv = *(const float4*)&Ws[k][tx * 4];
            float xv[4];
            #pragma unroll
            for (int i = 0; i < 4; i++) xv[i] = Xs[ty * 4 + i][k];
            #pragma unroll
            for (int i = 0; i < 4; i++) {
                acc[i][0] = fmaf(xv[i], wv.x, acc[i][0]);
                acc[i][1] = fmaf(xv[i], wv.y, acc[i][1]);
                acc[i][2] = fmaf(xv[i], wv.z, acc[i][2]);
                acc[i][3] = fmaf(xv[i], wv.w, acc[i][3]);
            }
        }
        __syncthreads();
    }
    #pragma unroll
    for (int i = 0; i < 4; i++) {
        int n = n0 + ty * 4 + i;
        if (n < N)
            *(float4*)(H + (size_t)n * 64 + tx * 4) =
                make_float4(acc[i][0], acc[i][1], acc[i][2], acc[i][3]);
    }
}

// ---------------- edge scatter: agg[dst] += h[src] * dinv[src]*dinv[dst] ----
// One thread per edge; vector reductions (red.global.add.v4.f32, sm_90+).
template <int D, int HS>
__global__ void scatter_kernel(const void* __restrict__ eidx,
                               const float* __restrict__ H,
                               const float* __restrict__ dinv,
                               float* __restrict__ agg, int E) {
    int e = blockIdx.x * blockDim.x + threadIdx.x;
    if (e >= E) return;
    int is64 = g_is64;
    int s = load_idx(eidx, e, is64);
    int d = load_idx(eidx, (long long)E + e, is64);
    float coef = dinv[s] * dinv[d];
    const float4* h = (const float4*)(H + (size_t)s * HS);
    float* a = agg + (size_t)d * D;
    #pragma unroll
    for (int q = 0; q < D / 4; q++) {
        float4 v = h[q];
        float vx = v.x * coef, vy = v.y * coef, vz = v.z * coef, vw = v.w * coef;
        asm volatile("red.global.add.v4.f32 [%0], {%1, %2, %3, %4};"
                     :: "l"(a + 4 * q), "f"(vx), "f"(vy), "f"(vz), "f"(vw)
                     : "memory");
    }
}

// ---------------- finalize: out = [relu](agg + h*dinv^2 + b) ----------------
template <int D, int HS, bool RELU>
__global__ void finalize_kernel(const float* __restrict__ agg, const float* __restrict__ H,
                                const float* __restrict__ dinv, const float* __restrict__ b,
                                float* __restrict__ out, int N) {
    int idx = blockIdx.x * blockDim.x + threadIdx.x;
    if (idx >= N * D) return;
    int n = idx / D, c = idx % D;
    float di = dinv[n];
    float v = agg[idx] + H[(size_t)n * HS + c] * (di * di) + b[c];
    out[idx] = RELU ? fmaxf(v, 0.0f) : v;
}

// ---------------- launch ----------------
extern "C" void kernel_launch(void* const* d_in, const int* in_sizes, int n_in,
                              void* d_out, int out_size) {
    const float* x    = (const float*)d_in[0];
    const void*  eidx = d_in[1];
    const float* W1   = (const float*)d_in[2];
    const float* b1   = (const float*)d_in[3];
    const float* W2   = (const float*)d_in[4];
    const float* b2   = (const float*)d_in[5];
    const float* W3   = (const float*)d_in[6];
    const float* b3   = (const float*)d_in[7];
    float* out = (float*)d_out;

    const int N = in_sizes[0] / D_IN;      // 100000
    const int E = in_sizes[1] / 2;         // 1600000

    float *ph, *pagg, *px, *pdeg, *pdinv, *pW3p;
    cudaGetSymbolAddress((void**)&ph,    g_h);
    cudaGetSymbolAddress((void**)&pagg,  g_agg);
    cudaGetSymbolAddress((void**)&px,    g_x);
    cudaGetSymbolAddress((void**)&pdeg,  g_deg);
    cudaGetSymbolAddress((void**)&pdinv, g_dinv);
    cudaGetSymbolAddress((void**)&pW3p,  g_W3p);

    const int TB = 256;
    const int eb = (E + TB - 1) / TB;
    const int gemm_blocks = (N + 63) / 64;

    // dtype detection + degree/norm
    detect_kernel<<<1, 32>>>((const unsigned*)eidx);
    zero_kernel<<<128, TB>>>((float4*)pdeg, N / 4);
    deg_kernel<<<eb, TB>>>(eidx, pdeg, E);
    dinv_kernel<<<(N + TB - 1) / TB, TB>>>(pdeg, pdinv, N);
    padW3_kernel<<<16, TB>>>(W3, pW3p);

    // ---- layer 1: 128 -> 64, relu ----
    gemm_kernel<128><<<gemm_blocks, TB>>>(x, W1, ph, N);
    zero_kernel<<<1024, TB>>>((float4*)pagg, N * 64 / 4);
    scatter_kernel<64, 64><<<eb, TB>>>(eidx, ph, pdinv, pagg, E);
    finalize_kernel<64, 64, true><<<(N * 64 + TB - 1) / TB, TB>>>(pagg, ph, pdinv, b1, px, N);

    // ---- layer 2: 64 -> 64, relu ----
    gemm_kernel<64><<<gemm_blocks, TB>>>(px, W2, ph, N);
    zero_kernel<<<1024, TB>>>((float4*)pagg, N * 64 / 4);
    scatter_kernel<64, 64><<<eb, TB>>>(eidx, ph, pdinv, pagg, E);
    finalize_kernel<64, 64, true><<<(N * 64 + TB - 1) / TB, TB>>>(pagg, ph, pdinv, b2, px, N);

    // ---- layer 3: 64 -> 40 (W padded to 64; h stride 64, cols 40..63 = 0) ----
    gemm_kernel<64><<<gemm_blocks, TB>>>(px, pW3p, ph, N);
    zero_kernel<<<1024, TB>>>((float4*)pagg, N * D_OUT / 4);
    scatter_kernel<D_OUT, 64><<<eb, TB>>>(eidx, ph, pdinv, pagg, E);
    finalize_kernel<D_OUT, 64, false><<<(N * D_OUT + TB - 1) / TB, TB>>>(pagg, ph, pdinv, b3, out, N);
}

// round 2
// speedup vs baseline: 2.1617x; 2.1617x over previous
#include <cuda_runtime.h>
#include <cuda_bf16.h>
#include <math.h>

#define MAXN 100000
#define MAXE 1600000
#define D_IN 128
#define D_OUT 40

// ---------------- static scratch ----------------
__device__ float g_u  [MAXN * 64];      // GEMM output scaled by dinv
__device__ float g_act[MAXN * 64];      // layer activation
__device__ float g_dinv[MAXN];
__device__ int   g_cnt[MAXN];
__device__ int   g_off[MAXN + 1];
__device__ int   g_cur[MAXN];
__device__ int   g_bsum[256];
__device__ int   g_esrc[MAXE];
__device__ float g_W3p[64 * 64];
__device__ int   g_is64;

// ---------------- edge dtype detection ----------------
__global__ void detect_kernel(const unsigned* __restrict__ w) {
    int nz = 0;
    for (int i = threadIdx.x; i < 4096; i += 32)
        if (w[2 * i + 1] != 0u) nz = 1;
    unsigned m = __ballot_sync(0xffffffffu, nz);
    if (threadIdx.x == 0) g_is64 = (m == 0u) ? 1 : 0;
}

__device__ __forceinline__ int load_idx(const void* p, long long e, int is64) {
    return is64 ? (int)((const long long*)p)[e] : ((const int*)p)[e];
}

// ---------------- preprocessing ----------------
__global__ void zero_cnt_kernel(int* __restrict__ cnt, int N) {
    int i = blockIdx.x * blockDim.x + threadIdx.x;
    if (i < N) cnt[i] = 0;
}

__global__ void count_kernel(const void* __restrict__ eidx, int* __restrict__ cnt, int E) {
    int e = blockIdx.x * blockDim.x + threadIdx.x;
    if (e >= E) return;
    int d = load_idx(eidx, (long long)E + e, g_is64);
    atomicAdd(&cnt[d], 1);
}

__global__ void dinv_kernel(const int* __restrict__ cnt, float* __restrict__ dinv, int N) {
    int i = blockIdx.x * blockDim.x + threadIdx.x;
    if (i < N) dinv[i] = rsqrtf((float)cnt[i] + 1.0f);
}

// block-wise exclusive scan (512 elems / block)
__global__ void scan1_kernel(const int* __restrict__ cnt, int* __restrict__ off,
                             int* __restrict__ bsum, int N) {
    __shared__ int sh[512];
    int tid = threadIdx.x;
    int gid = blockIdx.x * 512 + tid;
    int v = (gid < N) ? cnt[gid] : 0;
    sh[tid] = v;
    __syncthreads();
    for (int d = 1; d < 512; d <<= 1) {
        int t = (tid >= d) ? sh[tid - d] : 0;
        __syncthreads();
        sh[tid] += t;
        __syncthreads();
    }
    if (gid < N) off[gid] = sh[tid] - v;
    if (tid == 511) bsum[blockIdx.x] = sh[511];
}

__global__ void scan2_kernel(int* __restrict__ bsum, int nb) {
    __shared__ int sh[512];
    int tid = threadIdx.x;
    int v = (tid < nb) ? bsum[tid] : 0;
    sh[tid] = v;
    __syncthreads();
    for (int d = 1; d < 512; d <<= 1) {
        int t = (tid >= d) ? sh[tid - d] : 0;
        __syncthreads();
        sh[tid] += t;
        __syncthreads();
    }
    if (tid < nb) bsum[tid] = sh[tid] - v;
}

__global__ void scan3_kernel(int* __restrict__ off, const int* __restrict__ bsum,
                             int* __restrict__ cur, int N, int E) {
    int gid = blockIdx.x * blockDim.x + threadIdx.x;
    if (gid < N) {
        int o = off[gid] + bsum[gid / 512];
        off[gid] = o;
        cur[gid] = o;
    }
    if (gid == 0) off[N] = E;
}

__global__ void bucket_kernel(const void* __restrict__ eidx, int* __restrict__ cur,
                              int* __restrict__ esrc, int E) {
    int e = blockIdx.x * blockDim.x + threadIdx.x;
    if (e >= E) return;
    int is64 = g_is64;
    int s = load_idx(eidx, e, is64);
    int d = load_idx(eidx, (long long)E + e, is64);
    int pos = atomicAdd(&cur[d], 1);
    esrc[pos] = s;
}

__global__ void padW3_kernel(const float* __restrict__ W3, float* __restrict__ Wp) {
    int i = blockIdx.x * blockDim.x + threadIdx.x;
    if (i < 64 * 64) {
        int r = i / 64, c = i % 64;
        Wp[i] = (c < D_OUT) ? W3[r * D_OUT + c] : 0.0f;
    }
}

// ---------------- GEMM: U[N,64] = (X[N,DIN] @ W[DIN,64]) * dinv[n] ----------
// 256 threads, tile 128 nodes x 64 cols, each thread 4 nodes x 8 cols.
template <int DIN>
__global__ void gemm_kernel(const float* __restrict__ X, const float* __restrict__ W,
                            const float* __restrict__ dinv, float* __restrict__ U, int N) {
    constexpr int BN = 128;
    constexpr int KC = 32;
    __shared__ float Xs[BN][KC + 1];
    __shared__ float Ws[KC][64];
    const int tid = threadIdx.x;
    const int tx = tid & 7;    // cols tx*8 .. tx*8+7
    const int ty = tid >> 3;   // nodes ty*4 .. ty*4+3
    const int n0 = blockIdx.x * BN;

    float acc[4][8] = {};

    for (int k0 = 0; k0 < DIN; k0 += KC) {
        // X tile: 128 x 32, float4 global loads, scalar STS (conflict-free via pad)
        #pragma unroll
        for (int i = tid; i < BN * (KC / 4); i += 256) {
            int row = i >> 3, c4 = i & 7;
            int n = n0 + row;
            float4 v = make_float4(0.f, 0.f, 0.f, 0.f);
            if (n < N) v = *(const float4*)(X + (size_t)n * DIN + k0 + c4 * 4);
            Xs[row][c4 * 4 + 0] = v.x;
            Xs[row][c4 * 4 + 1] = v.y;
            Xs[row][c4 * 4 + 2] = v.z;
            Xs[row][c4 * 4 + 3] = v.w;
        }
        // W tile: 32 x 64
        #pragma unroll
        for (int i = tid; i < KC * 16; i += 256) {
            int r = i >> 4, c4 = i & 15;
            *(float4*)&Ws[r][c4 * 4] = *(const float4*)(W + (size_t)(k0 + r) * 64 + c4 * 4);
        }
        __syncthreads();
        #pragma unroll
        for (int k = 0; k < KC; k++) {
            float4 w0 = *(const float4*)&Ws[k][tx * 8];
            float4 w1 = *(const float4*)&Ws[k][tx * 8 + 4];
            #pragma unroll
            for (int i = 0; i < 4; i++) {
                float xv = Xs[ty * 4 + i][k];
                acc[i][0] = fmaf(xv, w0.x, acc[i][0]);
                acc[i][1] = fmaf(xv, w0.y, acc[i][1]);
                acc[i][2] = fmaf(xv, w0.z, acc[i][2]);
                acc[i][3] = fmaf(xv, w0.w, acc[i][3]);
                acc[i][4] = fmaf(xv, w1.x, acc[i][4]);
                acc[i][5] = fmaf(xv, w1.y, acc[i][5]);
                acc[i][6] = fmaf(xv, w1.z, acc[i][6]);
                acc[i][7] = fmaf(xv, w1.w, acc[i][7]);
            }
        }
        __syncthreads();
    }
    #pragma unroll
    for (int i = 0; i < 4; i++) {
        int n = n0 + ty * 4 + i;
        if (n < N) {
            float di = dinv[n];
            float4 o0 = make_float4(acc[i][0] * di, acc[i][1] * di, acc[i][2] * di, acc[i][3] * di);
            float4 o1 = make_float4(acc[i][4] * di, acc[i][5] * di, acc[i][6] * di, acc[i][7] * di);
            *(float4*)(U + (size_t)n * 64 + tx * 8)     = o0;
            *(float4*)(U + (size_t)n * 64 + tx * 8 + 4) = o1;
        }
    }
}

// ---------------- CSR gather-aggregate ----------------
// out[n, c] = [relu]( dinv[n] * ( sum_{e in row n} u[src_e, c] + u[n, c] ) + b[c] )
// One warp per dst node; lane handles cols lane and lane+32. 2-edge software pipeline.
template <int OUTD, bool RELU>
__global__ void agg_kernel(const int* __restrict__ esrc, const int* __restrict__ off,
                           const float* __restrict__ u, const float* __restrict__ dinv,
                           const float* __restrict__ b, float* __restrict__ out, int N) {
    int w = (blockIdx.x * blockDim.x + threadIdx.x) >> 5;
    if (w >= N) return;
    int lane = threadIdx.x & 31;
    int s0 = off[w], s1 = off[w + 1];

    float acc0 = u[(size_t)w * 64 + lane];        // self-loop term
    float acc1 = u[(size_t)w * 64 + 32 + lane];

    for (int base = s0; base < s1; base += 32) {
        int m = min(32, s1 - base);
        int myS = (lane < m) ? esrc[base + lane] : 0;
        int j = 0;
        for (; j + 1 < m; j += 2) {
            int sA = __shfl_sync(0xffffffffu, myS, j);
            int sB = __shfl_sync(0xffffffffu, myS, j + 1);
            float a0 = u[(size_t)sA * 64 + lane];
            float a1 = u[(size_t)sA * 64 + 32 + lane];
            float c0 = u[(size_t)sB * 64 + lane];
            float c1 = u[(size_t)sB * 64 + 32 + lane];
            acc0 += a0; acc1 += a1;
            acc0 += c0; acc1 += c1;
        }
        if (j < m) {
            int sA = __shfl_sync(0xffffffffu, myS, j);
            acc0 += u[(size_t)sA * 64 + lane];
            acc1 += u[(size_t)sA * 64 + 32 + lane];
        }
    }

    float di = dinv[w];
    float r0 = acc0 * di + b[lane];
    if (RELU) r0 = fmaxf(r0, 0.0f);
    float* o = out + (size_t)w * OUTD;
    o[lane] = r0;
    if (lane + 32 < OUTD) {
        float r1 = acc1 * di + b[lane + 32];
        if (RELU) r1 = fmaxf(r1, 0.0f);
        o[lane + 32] = r1;
    }
}

// ---------------- launch ----------------
extern "C" void kernel_launch(void* const* d_in, const int* in_sizes, int n_in,
                              void* d_out, int out_size) {
    const float* x    = (const float*)d_in[0];
    const void*  eidx = d_in[1];
    const float* W1   = (const float*)d_in[2];
    const float* b1   = (const float*)d_in[3];
    const float* W2   = (const float*)d_in[4];
    const float* b2   = (const float*)d_in[5];
    const float* W3   = (const float*)d_in[6];
    const float* b3   = (const float*)d_in[7];
    float* out = (float*)d_out;

    const int N = in_sizes[0] / D_IN;   // 100000
    const int E = in_sizes[1] / 2;      // 1600000

    float *pu, *pact, *pdinv, *pW3p;
    int *pcnt, *poff, *pcur, *pbsum, *pesrc;
    cudaGetSymbolAddress((void**)&pu,    g_u);
    cudaGetSymbolAddress((void**)&pact,  g_act);
    cudaGetSymbolAddress((void**)&pdinv, g_dinv);
    cudaGetSymbolAddress((void**)&pW3p,  g_W3p);
    cudaGetSymbolAddress((void**)&pcnt,  g_cnt);
    cudaGetSymbolAddress((void**)&poff,  g_off);
    cudaGetSymbolAddress((void**)&pcur,  g_cur);
    cudaGetSymbolAddress((void**)&pbsum, g_bsum);
    cudaGetSymbolAddress((void**)&pesrc, g_esrc);

    const int TB = 256;
    const int eb = (E + TB - 1) / TB;
    const int nb = (N + TB - 1) / TB;
    const int nscan = (N + 511) / 512;
    const int gemm_blocks = (N + 127) / 128;
    const int agg_blocks = (N + 7) / 8;   // 8 warps / block

    // preprocessing: dtype, degree, dinv, CSR build
    detect_kernel<<<1, 32>>>((const unsigned*)eidx);
    zero_cnt_kernel<<<nb, TB>>>(pcnt, N);
    count_kernel<<<eb, TB>>>(eidx, pcnt, E);
    dinv_kernel<<<nb, TB>>>(pcnt, pdinv, N);
    scan1_kernel<<<nscan, 512>>>(pcnt, poff, pbsum, N);
    scan2_kernel<<<1, 512>>>(pbsum, nscan);
    scan3_kernel<<<nb, TB>>>(poff, pbsum, pcur, N, E);
    bucket_kernel<<<eb, TB>>>(eidx, pcur, pesrc, E);
    padW3_kernel<<<16, TB>>>(W3, pW3p);

    // layer 1: 128 -> 64, relu
    gemm_kernel<128><<<gemm_blocks, TB>>>(x, W1, pdinv, pu, N);
    agg_kernel<64, true><<<agg_blocks, TB>>>(pesrc, poff, pu, pdinv, b1, pact, N);

    // layer 2: 64 -> 64, relu
    gemm_kernel<64><<<gemm_blocks, TB>>>(pact, W2, pdinv, pu, N);
    agg_kernel<64, true><<<agg_blocks, TB>>>(pesrc, poff, pu, pdinv, b2, pact, N);

    // layer 3: 64 -> 40 (padded weights; u cols 40..63 are zero, never written)
    gemm_kernel<64><<<gemm_blocks, TB>>>(pact, pW3p, pdinv, pu, N);
    agg_kernel<40, false><<<agg_blocks, TB>>>(pesrc, poff, pu, pdinv, b3, out, N);
}

// round 4
// speedup vs baseline: 2.3563x; 1.0900x over previous
#include <cuda_runtime.h>
#include <cuda_fp16.h>
#include <math.h>

#define MAXN 100000
#define MAXE 1600000
#define D_IN 128
#define D_OUT 40

// ---------------- static scratch ----------------
__device__ __half2 g_u [MAXN * 32];     // GEMM output * dinv, fp16 packed (row = 32 half2)
__device__ float  g_act[MAXN * 64];     // layer activation (fp32)
__device__ float  g_dinv[MAXN];
__device__ int    g_cnt[MAXN];
__device__ int    g_off[MAXN + 1];
__device__ int    g_cur[MAXN];
__device__ int    g_bsum[256];
__device__ int    g_esrc[MAXE];
__device__ float  g_W3p[64 * 64];
__device__ int    g_is64;

// ---------------- init: zero counters + edge dtype detection ----------------
__global__ void init_kernel(const unsigned* __restrict__ w, int* __restrict__ cnt, int N) {
    int i = blockIdx.x * blockDim.x + threadIdx.x;
    if (i < N) cnt[i] = 0;
    if (blockIdx.x == 0 && threadIdx.x < 32) {
        int nz = 0;
        for (int k = threadIdx.x; k < 4096; k += 32)
            if (w[2 * k + 1] != 0u) nz = 1;
        unsigned m = __ballot_sync(0xffffffffu, nz);
        if (threadIdx.x == 0) g_is64 = (m == 0u) ? 1 : 0;
    }
}

__device__ __forceinline__ int load_idx(const void* p, long long e, int is64) {
    return is64 ? (int)((const long long*)p)[e] : ((const int*)p)[e];
}

// ---------------- preprocessing ----------------
__global__ void count_kernel(const void* __restrict__ eidx, int* __restrict__ cnt, int E) {
    int e = blockIdx.x * blockDim.x + threadIdx.x;
    if (e >= E) return;
    int d = load_idx(eidx, (long long)E + e, g_is64);
    atomicAdd(&cnt[d], 1);
}

__global__ void dinv_kernel(const int* __restrict__ cnt, float* __restrict__ dinv, int N) {
    int i = blockIdx.x * blockDim.x + threadIdx.x;
    if (i < N) dinv[i] = rsqrtf((float)cnt[i] + 1.0f);
}

__global__ void scan1_kernel(const int* __restrict__ cnt, int* __restrict__ off,
                             int* __restrict__ bsum, int N) {
    __shared__ int sh[512];
    int tid = threadIdx.x;
    int gid = blockIdx.x * 512 + tid;
    int v = (gid < N) ? cnt[gid] : 0;
    sh[tid] = v;
    __syncthreads();
    for (int d = 1; d < 512; d <<= 1) {
        int t = (tid >= d) ? sh[tid - d] : 0;
        __syncthreads();
        sh[tid] += t;
        __syncthreads();
    }
    if (gid < N) off[gid] = sh[tid] - v;
    if (tid == 511) bsum[blockIdx.x] = sh[511];
}

__global__ void scan2_kernel(int* __restrict__ bsum, int nb) {
    __shared__ int sh[512];
    int tid = threadIdx.x;
    int v = (tid < nb) ? bsum[tid] : 0;
    sh[tid] = v;
    __syncthreads();
    for (int d = 1; d < 512; d <<= 1) {
        int t = (tid >= d) ? sh[tid - d] : 0;
        __syncthreads();
        sh[tid] += t;
        __syncthreads();
    }
    if (tid < nb) bsum[tid] = sh[tid] - v;
}

__global__ void scan3_kernel(int* __restrict__ off, const int* __restrict__ bsum,
                             int* __restrict__ cur, int N, int E) {
    int gid = blockIdx.x * blockDim.x + threadIdx.x;
    if (gid < N) {
        int o = off[gid] + bsum[gid / 512];
        off[gid] = o;
        cur[gid] = o;
    }
    if (gid == 0) off[N] = E;
}

__global__ void bucket_kernel(const void* __restrict__ eidx, int* __restrict__ cur,
                              int* __restrict__ esrc, int E) {
    int e = blockIdx.x * blockDim.x + threadIdx.x;
    if (e >= E) return;
    int is64 = g_is64;
    int s = load_idx(eidx, e, is64);
    int d = load_idx(eidx, (long long)E + e, is64);
    int pos = atomicAdd(&cur[d], 1);
    esrc[pos] = s;
}

__global__ void padW3_kernel(const float* __restrict__ W3, float* __restrict__ Wp) {
    int i = blockIdx.x * blockDim.x + threadIdx.x;
    if (i < 64 * 64) {
        int r = i / 64, c = i % 64;
        Wp[i] = (c < D_OUT) ? W3[r * D_OUT + c] : 0.0f;
    }
}

// ---------------- GEMM: U[N,64] = fp16( (X[N,DIN] @ W[DIN,64]) * dinv[n] ) ----
// 256 threads, tile 128 nodes x 64 cols, each thread 4 nodes x 8 cols.
template <int DIN>
__global__ void gemm_kernel(const float* __restrict__ X, const float* __restrict__ W,
                            const float* __restrict__ dinv, __half2* __restrict__ U, int N) {
    constexpr int BN = 128;
    constexpr int KC = 32;
    __shared__ float Xs[BN][KC + 1];
    __shared__ float Ws[KC][64];
    const int tid = threadIdx.x;
    const int tx = tid & 7;    // cols tx*8 .. tx*8+7
    const int ty = tid >> 3;   // nodes ty*4 .. ty*4+3
    const int n0 = blockIdx.x * BN;

    float acc[4][8] = {};

    for (int k0 = 0; k0 < DIN; k0 += KC) {
        #pragma unroll
        for (int i = tid; i < BN * (KC / 4); i += 256) {
            int row = i >> 3, c4 = i & 7;
            int n = n0 + row;
            float4 v = make_float4(0.f, 0.f, 0.f, 0.f);
            if (n < N) v = *(const float4*)(X + (size_t)n * DIN + k0 + c4 * 4);
            Xs[row][c4 * 4 + 0] = v.x;
            Xs[row][c4 * 4 + 1] = v.y;
            Xs[row][c4 * 4 + 2] = v.z;
            Xs[row][c4 * 4 + 3] = v.w;
        }
        #pragma unroll
        for (int i = tid; i < KC * 16; i += 256) {
            int r = i >> 4, c4 = i & 15;
            *(float4*)&Ws[r][c4 * 4] = *(const float4*)(W + (size_t)(k0 + r) * 64 + c4 * 4);
        }
        __syncthreads();
        #pragma unroll
        for (int k = 0; k < KC; k++) {
            float4 w0 = *(const float4*)&Ws[k][tx * 8];
            float4 w1 = *(const float4*)&Ws[k][tx * 8 + 4];
            #pragma unroll
            for (int i = 0; i < 4; i++) {
                float xv = Xs[ty * 4 + i][k];
                acc[i][0] = fmaf(xv, w0.x, acc[i][0]);
                acc[i][1] = fmaf(xv, w0.y, acc[i][1]);
                acc[i][2] = fmaf(xv, w0.z, acc[i][2]);
                acc[i][3] = fmaf(xv, w0.w, acc[i][3]);
                acc[i][4] = fmaf(xv, w1.x, acc[i][4]);
                acc[i][5] = fmaf(xv, w1.y, acc[i][5]);
                acc[i][6] = fmaf(xv, w1.z, acc[i][6]);
                acc[i][7] = fmaf(xv, w1.w, acc[i][7]);
            }
        }
        __syncthreads();
    }
    #pragma unroll
    for (int i = 0; i < 4; i++) {
        int n = n0 + ty * 4 + i;
        if (n < N) {
            float di = dinv[n];
            __half2 hv[4];
            #pragma unroll
            for (int q = 0; q < 4; q++)
                hv[q] = __floats2half2_rn(acc[i][2 * q] * di, acc[i][2 * q + 1] * di);
            // 16B packed store of 4 half2 (cols tx*8 .. tx*8+7)
            *(uint4*)(U + (size_t)n * 32 + tx * 4) = *(const uint4*)hv;
        }
    }
}

// ---------------- CSR gather-aggregate (fp16 u, fp32 accum) ----------------
// out[n, c] = [relu]( dinv[n] * ( sum_{e in row n} u[src_e, c] + u[n, c] ) + b[c] )
// One warp per dst node; lane covers column pair (2*lane, 2*lane+1).
template <int OUTD, bool RELU>
__global__ void agg_kernel(const int* __restrict__ esrc, const int* __restrict__ off,
                           const __half2* __restrict__ u, const float* __restrict__ dinv,
                           const float* __restrict__ b, float* __restrict__ out, int N) {
    int w = (blockIdx.x * blockDim.x + threadIdx.x) >> 5;
    if (w >= N) return;
    int lane = threadIdx.x & 31;
    int s0 = off[w], s1 = off[w + 1];

    float2 acc = __half22float2(u[(size_t)w * 32 + lane]);  // self-loop term

    for (int base = s0; base < s1; base += 32) {
        int m = min(32, s1 - base);
        int myS = (lane < m) ? esrc[base + lane] : 0;
        int j = 0;
        for (; j + 3 < m; j += 4) {
            int sA = __shfl_sync(0xffffffffu, myS, j);
            int sB = __shfl_sync(0xffffffffu, myS, j + 1);
            int sC = __shfl_sync(0xffffffffu, myS, j + 2);
            int sD = __shfl_sync(0xffffffffu, myS, j + 3);
            __half2 vA = u[(size_t)sA * 32 + lane];
            __half2 vB = u[(size_t)sB * 32 + lane];
            __half2 vC = u[(size_t)sC * 32 + lane];
            __half2 vD = u[(size_t)sD * 32 + lane];
            float2 fA = __half22float2(vA);
            float2 fB = __half22float2(vB);
            float2 fC = __half22float2(vC);
            float2 fD = __half22float2(vD);
            acc.x += (fA.x + fB.x) + (fC.x + fD.x);
            acc.y += (fA.y + fB.y) + (fC.y + fD.y);
        }
        for (; j < m; j++) {
            int sA = __shfl_sync(0xffffffffu, myS, j);
            float2 fA = __half22float2(u[(size_t)sA * 32 + lane]);
            acc.x += fA.x;
            acc.y += fA.y;
        }
    }

    if (2 * lane < OUTD) {
        float di = dinv[w];
        float r0 = acc.x * di + b[2 * lane];
        float r1 = acc.y * di + b[2 * lane + 1];
        if (RELU) { r0 = fmaxf(r0, 0.0f); r1 = fmaxf(r1, 0.0f); }
        *(float2*)(out + (size_t)w * OUTD + 2 * lane) = make_float2(r0, r1);
    }
}

// ---------------- launch ----------------
extern "C" void kernel_launch(void* const* d_in, const int* in_sizes, int n_in,
                              void* d_out, int out_size) {
    const float* x    = (const float*)d_in[0];
    const void*  eidx = d_in[1];
    const float* W1   = (const float*)d_in[2];
    const float* b1   = (const float*)d_in[3];
    const float* W2   = (const float*)d_in[4];
    const float* b2   = (const float*)d_in[5];
    const float* W3   = (const float*)d_in[6];
    const float* b3   = (const float*)d_in[7];
    float* out = (float*)d_out;

    const int N = in_sizes[0] / D_IN;   // 100000
    const int E = in_sizes[1] / 2;      // 1600000

    __half2* pu;
    float *pact, *pdinv, *pW3p;
    int *pcnt, *poff, *pcur, *pbsum, *pesrc;
    cudaGetSymbolAddress((void**)&pu,    g_u);
    cudaGetSymbolAddress((void**)&pact,  g_act);
    cudaGetSymbolAddress((void**)&pdinv, g_dinv);
    cudaGetSymbolAddress((void**)&pW3p,  g_W3p);
    cudaGetSymbolAddress((void**)&pcnt,  g_cnt);
    cudaGetSymbolAddress((void**)&poff,  g_off);
    cudaGetSymbolAddress((void**)&pcur,  g_cur);
    cudaGetSymbolAddress((void**)&pbsum, g_bsum);
    cudaGetSymbolAddress((void**)&pesrc, g_esrc);

    const int TB = 256;
    const int eb = (E + TB - 1) / TB;
    const int nb = (N + TB - 1) / TB;
    const int nscan = (N + 511) / 512;
    const int gemm_blocks = (N + 127) / 128;
    const int agg_blocks = (N + 7) / 8;   // 8 warps / block

    // preprocessing: dtype+zero, degree, dinv, CSR build
    init_kernel<<<nb, TB>>>((const unsigned*)eidx, pcnt, N);
    count_kernel<<<eb, TB>>>(eidx, pcnt, E);
    dinv_kernel<<<nb, TB>>>(pcnt, pdinv, N);
    scan1_kernel<<<nscan, 512>>>(pcnt, poff, pbsum, N);
    scan2_kernel<<<1, 512>>>(pbsum, nscan);
    scan3_kernel<<<nb, TB>>>(poff, pbsum, pcur, N, E);
    bucket_kernel<<<eb, TB>>>(eidx, pcur, pesrc, E);
    padW3_kernel<<<16, TB>>>(W3, pW3p);

    // layer 1: 128 -> 64, relu
    gemm_kernel<128><<<gemm_blocks, TB>>>(x, W1, pdinv, pu, N);
    agg_kernel<64, true><<<agg_blocks, TB>>>(pesrc, poff, pu, pdinv, b1, pact, N);

    // layer 2: 64 -> 64, relu
    gemm_kernel<64><<<gemm_blocks, TB>>>(pact, W2, pdinv, pu, N);
    agg_kernel<64, true><<<agg_blocks, TB>>>(pesrc, poff, pu, pdinv, b2, pact, N);

    // layer 3: 64 -> 40 (padded weights; u cols 40..63 are zero)
    gemm_kernel<64><<<gemm_blocks, TB>>>(pact, pW3p, pdinv, pu, N);
    agg_kernel<40, false><<<agg_blocks, TB>>>(pesrc, poff, pu, pdinv, b3, out, N);
}

// round 5
// speedup vs baseline: 3.4161x; 1.4498x over previous
#include <cuda_runtime.h>
#include <cuda_fp16.h>
#include <math.h>

#define MAXN 100000
#define MAXE 1600000
#define D_IN 128
#define D_OUT 40

// ---------------- static scratch ----------------
__device__ __half2 g_u [MAXN * 32];     // GEMM output * dinv, fp16 packed (row = 32 half2)
__device__ float  g_act[MAXN * 64];     // layer activation (fp32)
__device__ float  g_dinv[MAXN];
__device__ int    g_cnt[MAXN];
__device__ int    g_off[MAXN + 1];
__device__ int    g_cur[MAXN];
__device__ int    g_bsum[256];
__device__ int    g_esrc[MAXE];
__device__ float  g_W3p[64 * 64];
__device__ int    g_is64;

// ---------------- init: zero counters + edge dtype detection ----------------
__global__ void init_kernel(const unsigned* __restrict__ w, int* __restrict__ cnt, int N) {
    int i = blockIdx.x * blockDim.x + threadIdx.x;
    if (i < N) cnt[i] = 0;
    if (blockIdx.x == 0 && threadIdx.x < 32) {
        int nz = 0;
        for (int k = threadIdx.x; k < 4096; k += 32)
            if (w[2 * k + 1] != 0u) nz = 1;
        unsigned m = __ballot_sync(0xffffffffu, nz);
        if (threadIdx.x == 0) g_is64 = (m == 0u) ? 1 : 0;
    }
}

__device__ __forceinline__ int load_idx(const void* p, long long e, int is64) {
    return is64 ? (int)((const long long*)p)[e] : ((const int*)p)[e];
}

// ---------------- preprocessing ----------------
__global__ void count_kernel(const void* __restrict__ eidx, int* __restrict__ cnt, int E) {
    int e = blockIdx.x * blockDim.x + threadIdx.x;
    if (e >= E) return;
    int d = load_idx(eidx, (long long)E + e, g_is64);
    atomicAdd(&cnt[d], 1);
}

__global__ void dinv_kernel(const int* __restrict__ cnt, float* __restrict__ dinv, int N) {
    int i = blockIdx.x * blockDim.x + threadIdx.x;
    if (i < N) dinv[i] = rsqrtf((float)cnt[i] + 1.0f);
}

__global__ void scan1_kernel(const int* __restrict__ cnt, int* __restrict__ off,
                             int* __restrict__ bsum, int N) {
    __shared__ int sh[512];
    int tid = threadIdx.x;
    int gid = blockIdx.x * 512 + tid;
    int v = (gid < N) ? cnt[gid] : 0;
    sh[tid] = v;
    __syncthreads();
    for (int d = 1; d < 512; d <<= 1) {
        int t = (tid >= d) ? sh[tid - d] : 0;
        __syncthreads();
        sh[tid] += t;
        __syncthreads();
    }
    if (gid < N) off[gid] = sh[tid] - v;
    if (tid == 511) bsum[blockIdx.x] = sh[511];
}

__global__ void scan2_kernel(int* __restrict__ bsum, int nb) {
    __shared__ int sh[512];
    int tid = threadIdx.x;
    int v = (tid < nb) ? bsum[tid] : 0;
    sh[tid] = v;
    __syncthreads();
    for (int d = 1; d < 512; d <<= 1) {
        int t = (tid >= d) ? sh[tid - d] : 0;
        __syncthreads();
        sh[tid] += t;
        __syncthreads();
    }
    if (tid < nb) bsum[tid] = sh[tid] - v;
}

__global__ void scan3_kernel(int* __restrict__ off, const int* __restrict__ bsum,
                             int* __restrict__ cur, int N, int E) {
    int gid = blockIdx.x * blockDim.x + threadIdx.x;
    if (gid < N) {
        int o = off[gid] + bsum[gid / 512];
        off[gid] = o;
        cur[gid] = o;
    }
    if (gid == 0) off[N] = E;
}

__global__ void bucket_kernel(const void* __restrict__ eidx, int* __restrict__ cur,
                              int* __restrict__ esrc, int E) {
    int e = blockIdx.x * blockDim.x + threadIdx.x;
    if (e >= E) return;
    int is64 = g_is64;
    int s = load_idx(eidx, e, is64);
    int d = load_idx(eidx, (long long)E + e, is64);
    int pos = atomicAdd(&cur[d], 1);
    esrc[pos] = s;
}

__global__ void padW3_kernel(const float* __restrict__ W3, float* __restrict__ Wp) {
    int i = blockIdx.x * blockDim.x + threadIdx.x;
    if (i < 64 * 64) {
        int r = i / 64, c = i % 64;
        Wp[i] = (c < D_OUT) ? W3[r * D_OUT + c] : 0.0f;
    }
}

// ---------------- tensor-core GEMM ----------------
// U[N,64] = fp16( (X[N,DIN] @ W[DIN,64]) * dinv[n] ), mma.sync m16n8k16 f16->f32.
// 256 threads (8 warps); block = 128 rows x 64 cols; K tiled in chunks of 64.
// Xs: [128][KC] halves (pad 8), Wt: W transposed n-major [64][KC] halves (pad 8).
template <int DIN>
__global__ void __launch_bounds__(256)
gemm_mma_kernel(const float* __restrict__ X, const float* __restrict__ W,
                const float* __restrict__ dinv, __half2* __restrict__ U, int N) {
    constexpr int KC = 64;
    constexpr int XP = KC + 8;   // 72 halves; row stride 144B (word stride 36 -> 4*grp+qu banks OK)
    __shared__ __half Xs[128][XP];
    __shared__ __half Wt[64][XP];

    const int tid  = threadIdx.x;
    const int wid  = tid >> 5;
    const int lane = tid & 31;
    const int grp  = lane >> 2;     // 0..7
    const int qu   = lane & 3;      // 0..3
    const int n0   = blockIdx.x * 128;
    const int r0   = wid * 16;      // warp's row offset within block

    float d[8][4] = {};             // 8 n-tiles of m16n8, 4 f32 each

    for (int kc0 = 0; kc0 < DIN; kc0 += KC) {
        // stage X chunk: 128 rows x 64 cols fp32 -> fp16 (float4 -> 4 halves = uint2)
        #pragma unroll
        for (int i = tid; i < 128 * (KC / 4); i += 256) {
            int row = i >> 4, c4 = (i & 15) * 4;
            int n = n0 + row;
            float4 v = make_float4(0.f, 0.f, 0.f, 0.f);
            if (n < N) v = *(const float4*)(X + (size_t)n * DIN + kc0 + c4);
            __half2 h0 = __floats2half2_rn(v.x, v.y);
            __half2 h1 = __floats2half2_rn(v.z, v.w);
            *(uint2*)&Xs[row][c4] = make_uint2(*(unsigned*)&h0, *(unsigned*)&h1);
        }
        // stage W chunk transposed: Wt[n][k] = W[kc0+k][n]
        #pragma unroll
        for (int i = tid; i < KC * 64; i += 256) {
            int k = i >> 6, n = i & 63;
            Wt[n][k] = __float2half_rn(W[(size_t)(kc0 + k) * 64 + n]);
        }
        __syncthreads();

        #pragma unroll
        for (int kk = 0; kk < KC; kk += 16) {
            // A fragment (shared across all 8 n-tiles)
            unsigned a0 = *(const unsigned*)&Xs[r0 + grp    ][kk + qu * 2    ];
            unsigned a1 = *(const unsigned*)&Xs[r0 + grp + 8][kk + qu * 2    ];
            unsigned a2 = *(const unsigned*)&Xs[r0 + grp    ][kk + qu * 2 + 8];
            unsigned a3 = *(const unsigned*)&Xs[r0 + grp + 8][kk + qu * 2 + 8];
            #pragma unroll
            for (int nt = 0; nt < 8; nt++) {
                unsigned b0 = *(const unsigned*)&Wt[nt * 8 + grp][kk + qu * 2    ];
                unsigned b1 = *(const unsigned*)&Wt[nt * 8 + grp][kk + qu * 2 + 8];
                asm volatile(
                    "mma.sync.aligned.m16n8k16.row.col.f32.f16.f16.f32 "
                    "{%0,%1,%2,%3}, {%4,%5,%6,%7}, {%8,%9}, {%0,%1,%2,%3};"
                    : "+f"(d[nt][0]), "+f"(d[nt][1]), "+f"(d[nt][2]), "+f"(d[nt][3])
                    : "r"(a0), "r"(a1), "r"(a2), "r"(a3), "r"(b0), "r"(b1));
            }
        }
        __syncthreads();
    }

    // epilogue: thread owns rows (r0+grp, r0+grp+8), cols nt*8 + qu*2, +1
    int rA = n0 + r0 + grp;
    int rB = rA + 8;
    float diA = (rA < N) ? dinv[rA] : 0.0f;
    float diB = (rB < N) ? dinv[rB] : 0.0f;
    #pragma unroll
    for (int nt = 0; nt < 8; nt++) {
        if (rA < N)
            U[(size_t)rA * 32 + nt * 4 + qu] = __floats2half2_rn(d[nt][0] * diA, d[nt][1] * diA);
        if (rB < N)
            U[(size_t)rB * 32 + nt * 4 + qu] = __floats2half2_rn(d[nt][2] * diB, d[nt][3] * diB);
    }
}

// ---------------- CSR gather-aggregate (fp16 u, fp32 accum) ----------------
// out[n, c] = [relu]( dinv[n] * ( sum_{e in row n} u[src_e, c] + u[n, c] ) + b[c] )
// One warp per dst node; lane covers column pair (2*lane, 2*lane+1).
// Lanes beyond OUTD skip the value gathers (indices still full-warp shuffled).
template <int OUTD, bool RELU>
__global__ void agg_kernel(const int* __restrict__ esrc, const int* __restrict__ off,
                           const __half2* __restrict__ u, const float* __restrict__ dinv,
                           const float* __restrict__ b, float* __restrict__ out, int N) {
    int w = (blockIdx.x * blockDim.x + threadIdx.x) >> 5;
    if (w >= N) return;
    int lane = threadIdx.x & 31;
    int s0 = off[w], s1 = off[w + 1];
    const bool active = (2 * lane < OUTD);

    float2 acc = make_float2(0.f, 0.f);
    if (active) acc = __half22float2(u[(size_t)w * 32 + lane]);  // self-loop term

    for (int base = s0; base < s1; base += 32) {
        int m = min(32, s1 - base);
        int myS = (lane < m) ? esrc[base + lane] : 0;
        int j = 0;
        for (; j + 3 < m; j += 4) {
            int sA = __shfl_sync(0xffffffffu, myS, j);
            int sB = __shfl_sync(0xffffffffu, myS, j + 1);
            int sC = __shfl_sync(0xffffffffu, myS, j + 2);
            int sD = __shfl_sync(0xffffffffu, myS, j + 3);
            if (active) {
                float2 fA = __half22float2(u[(size_t)sA * 32 + lane]);
                float2 fB = __half22float2(u[(size_t)sB * 32 + lane]);
                float2 fC = __half22float2(u[(size_t)sC * 32 + lane]);
                float2 fD = __half22float2(u[(size_t)sD * 32 + lane]);
                acc.x += (fA.x + fB.x) + (fC.x + fD.x);
                acc.y += (fA.y + fB.y) + (fC.y + fD.y);
            }
        }
        for (; j < m; j++) {
            int sA = __shfl_sync(0xffffffffu, myS, j);
            if (active) {
                float2 fA = __half22float2(u[(size_t)sA * 32 + lane]);
                acc.x += fA.x;
                acc.y += fA.y;
            }
        }
    }

    if (active) {
        float di = dinv[w];
        float r0 = acc.x * di + b[2 * lane];
        float r1 = acc.y * di + b[2 * lane + 1];
        if (RELU) { r0 = fmaxf(r0, 0.0f); r1 = fmaxf(r1, 0.0f); }
        *(float2*)(out + (size_t)w * OUTD + 2 * lane) = make_float2(r0, r1);
    }
}

// ---------------- launch ----------------
extern "C" void kernel_launch(void* const* d_in, const int* in_sizes, int n_in,
                              void* d_out, int out_size) {
    const float* x    = (const float*)d_in[0];
    const void*  eidx = d_in[1];
    const float* W1   = (const float*)d_in[2];
    const float* b1   = (const float*)d_in[3];
    const float* W2   = (const float*)d_in[4];
    const float* b2   = (const float*)d_in[5];
    const float* W3   = (const float*)d_in[6];
    const float* b3   = (const float*)d_in[7];
    float* out = (float*)d_out;

    const int N = in_sizes[0] / D_IN;   // 100000
    const int E = in_sizes[1] / 2;      // 1600000

    __half2* pu;
    float *pact, *pdinv, *pW3p;
    int *pcnt, *poff, *pcur, *pbsum, *pesrc;
    cudaGetSymbolAddress((void**)&pu,    g_u);
    cudaGetSymbolAddress((void**)&pact,  g_act);
    cudaGetSymbolAddress((void**)&pdinv, g_dinv);
    cudaGetSymbolAddress((void**)&pW3p,  g_W3p);
    cudaGetSymbolAddress((void**)&pcnt,  g_cnt);
    cudaGetSymbolAddress((void**)&poff,  g_off);
    cudaGetSymbolAddress((void**)&pcur,  g_cur);
    cudaGetSymbolAddress((void**)&pbsum, g_bsum);
    cudaGetSymbolAddress((void**)&pesrc, g_esrc);

    const int TB = 256;
    const int eb = (E + TB - 1) / TB;
    const int nb = (N + TB - 1) / TB;
    const int nscan = (N + 511) / 512;
    const int gemm_blocks = (N + 127) / 128;
    const int agg_blocks = (N + 7) / 8;   // 8 warps / block

    // preprocessing: dtype+zero, degree, dinv, CSR build
    init_kernel<<<nb, TB>>>((const unsigned*)eidx, pcnt, N);
    count_kernel<<<eb, TB>>>(eidx, pcnt, E);
    dinv_kernel<<<nb, TB>>>(pcnt, pdinv, N);
    scan1_kernel<<<nscan, 512>>>(pcnt, poff, pbsum, N);
    scan2_kernel<<<1, 512>>>(pbsum, nscan);
    scan3_kernel<<<nb, TB>>>(poff, pbsum, pcur, N, E);
    bucket_kernel<<<eb, TB>>>(eidx, pcur, pesrc, E);
    padW3_kernel<<<16, TB>>>(W3, pW3p);

    // layer 1: 128 -> 64, relu
    gemm_mma_kernel<128><<<gemm_blocks, TB>>>(x, W1, pdinv, pu, N);
    agg_kernel<64, true><<<agg_blocks, TB>>>(pesrc, poff, pu, pdinv, b1, pact, N);

    // layer 2: 64 -> 64, relu
    gemm_mma_kernel<64><<<gemm_blocks, TB>>>(pact, W2, pdinv, pu, N);
    agg_kernel<64, true><<<agg_blocks, TB>>>(pesrc, poff, pu, pdinv, b2, pact, N);

    // layer 3: 64 -> 40 (padded weights; u cols 40..63 are zero)
    gemm_mma_kernel<64><<<gemm_blocks, TB>>>(pact, pW3p, pdinv, pu, N);
    agg_kernel<40, false><<<agg_blocks, TB>>>(pesrc, poff, pu, pdinv, b3, out, N);
}

// round 6
// speedup vs baseline: 3.5800x; 1.0480x over previous
#include <cuda_runtime.h>
#include <cuda_fp16.h>
#include <math.h>

#define MAXN 100000
#define MAXE 1600000
#define D_IN 128
#define D_OUT 40

// ---------------- static scratch ----------------
__device__ __half2 g_u  [MAXN * 32];    // GEMM output * dinv, fp16 packed
__device__ __half2 g_act[MAXN * 32];    // layer activation, fp16 packed
__device__ float  g_dinv[MAXN];
__device__ int    g_cnt[MAXN];
__device__ int    g_off[MAXN + 1];
__device__ int    g_cur[MAXN];
__device__ int    g_bsum[256];
__device__ int    g_esrc[MAXE];
__device__ float  g_W3p[64 * 64];
__device__ int    g_is64;

// ---------------- init: zero cnt + detect dtype + pad W3 ----------------
__global__ void init_kernel(const unsigned* __restrict__ w, int* __restrict__ cnt,
                            const float* __restrict__ W3, float* __restrict__ Wp, int N) {
    int i = blockIdx.x * blockDim.x + threadIdx.x;
    if (i < N) cnt[i] = 0;
    if (i < 64 * 64) {
        int r = i / 64, c = i % 64;
        Wp[i] = (c < D_OUT) ? W3[r * D_OUT + c] : 0.0f;
    }
    if (blockIdx.x == 0 && threadIdx.x < 32) {
        int nz = 0;
        for (int k = threadIdx.x; k < 4096; k += 32)
            if (w[2 * k + 1] != 0u) nz = 1;
        unsigned m = __ballot_sync(0xffffffffu, nz);
        if (threadIdx.x == 0) g_is64 = (m == 0u) ? 1 : 0;
    }
}

__device__ __forceinline__ int load_idx(const void* p, long long e, int is64) {
    return is64 ? (int)((const long long*)p)[e] : ((const int*)p)[e];
}

// ---------------- preprocessing ----------------
__global__ void count_kernel(const void* __restrict__ eidx, int* __restrict__ cnt, int E) {
    int e = blockIdx.x * blockDim.x + threadIdx.x;
    if (e >= E) return;
    int d = load_idx(eidx, (long long)E + e, g_is64);
    atomicAdd(&cnt[d], 1);
}

// scanA: per-block (512) inclusive scan of cnt; writes local-exclusive off + block sums
__global__ void scanA_kernel(const int* __restrict__ cnt, int* __restrict__ off,
                             int* __restrict__ bsum, int N) {
    __shared__ int sh[512];
    int tid = threadIdx.x;
    int gid = blockIdx.x * 512 + tid;
    int v = (gid < N) ? cnt[gid] : 0;
    sh[tid] = v;
    __syncthreads();
    for (int d = 1; d < 512; d <<= 1) {
        int t = (tid >= d) ? sh[tid - d] : 0;
        __syncthreads();
        sh[tid] += t;
        __syncthreads();
    }
    if (gid < N) off[gid] = sh[tid] - v;
    if (tid == 511) bsum[blockIdx.x] = sh[511];
}

// scanB: each block reduces bsum[0..bid) itself, then finalizes off/cur/dinv.
// Assumes gridDim.x <= 512 (196 here).
__global__ void scanB_kernel(int* __restrict__ off, const int* __restrict__ bsum,
                             int* __restrict__ cur, float* __restrict__ dinv,
                             const int* __restrict__ cnt, int N, int E) {
    __shared__ int sh[512];
    int tid = threadIdx.x, bid = blockIdx.x;
    sh[tid] = (tid < bid) ? bsum[tid] : 0;
    __syncthreads();
    for (int s = 256; s > 0; s >>= 1) {
        if (tid < s) sh[tid] += sh[tid + s];
        __syncthreads();
    }
    int prefix = sh[0];
    int gid = bid * 512 + tid;
    if (gid < N) {
        int o = off[gid] + prefix;
        off[gid] = o;
        cur[gid] = o;
        dinv[gid] = rsqrtf((float)cnt[gid] + 1.0f);
    }
    if (gid == 0) off[N] = E;
}

__global__ void bucket_kernel(const void* __restrict__ eidx, int* __restrict__ cur,
                              int* __restrict__ esrc, int E) {
    int e = blockIdx.x * blockDim.x + threadIdx.x;
    if (e >= E) return;
    int is64 = g_is64;
    int s = load_idx(eidx, e, is64);
    int d = load_idx(eidx, (long long)E + e, is64);
    int pos = atomicAdd(&cur[d], 1);
    esrc[pos] = s;
}

// ---------------- tensor-core GEMM ----------------
// U[N,64] = fp16( (X[N,DIN] @ W[DIN,64]) * dinv[n] ), mma.sync m16n8k16 f16->f32.
// 256 threads (8 warps); block = 128 rows x 64 cols; K chunks of 64.
// HALF_IN: X is __half2 packed (row = DIN/2 half2); else fp32.
template <int DIN, bool HALF_IN>
__global__ void __launch_bounds__(256)
gemm_mma_kernel(const void* __restrict__ Xv, const float* __restrict__ W,
                const float* __restrict__ dinv, __half2* __restrict__ U, int N) {
    constexpr int KC = 64;
    constexpr int XP = KC + 8;   // 72 halves; row stride 144B (div by 16 -> uint4-safe)
    __shared__ __half Xs[128][XP];
    __shared__ __half Wt[64][XP];

    const int tid  = threadIdx.x;
    const int wid  = tid >> 5;
    const int lane = tid & 31;
    const int grp  = lane >> 2;
    const int qu   = lane & 3;
    const int n0   = blockIdx.x * 128;
    const int r0   = wid * 16;

    float d[8][4] = {};

    for (int kc0 = 0; kc0 < DIN; kc0 += KC) {
        if (HALF_IN) {
            // X already fp16: copy uint4 (8 halves) per iteration
            const uint4* Xh = (const uint4*)Xv;   // row = DIN/8 uint4
            #pragma unroll
            for (int i = tid; i < 128 * (KC / 8); i += 256) {
                int row = i >> 3, c8 = (i & 7);
                int n = n0 + row;
                uint4 v = make_uint4(0u, 0u, 0u, 0u);
                if (n < N) v = Xh[(size_t)n * (DIN / 8) + (kc0 / 8) + c8];
                *(uint4*)&Xs[row][c8 * 8] = v;
            }
        } else {
            const float* X = (const float*)Xv;
            #pragma unroll
            for (int i = tid; i < 128 * (KC / 4); i += 256) {
                int row = i >> 4, c4 = (i & 15) * 4;
                int n = n0 + row;
                float4 v = make_float4(0.f, 0.f, 0.f, 0.f);
                if (n < N) v = *(const float4*)(X + (size_t)n * DIN + kc0 + c4);
                __half2 h0 = __floats2half2_rn(v.x, v.y);
                __half2 h1 = __floats2half2_rn(v.z, v.w);
                *(uint2*)&Xs[row][c4] = make_uint2(*(unsigned*)&h0, *(unsigned*)&h1);
            }
        }
        // W chunk transposed n-major: Wt[n][k] = W[kc0+k][n]
        #pragma unroll
        for (int i = tid; i < KC * 64; i += 256) {
            int k = i >> 6, n = i & 63;
            Wt[n][k] = __float2half_rn(W[(size_t)(kc0 + k) * 64 + n]);
        }
        __syncthreads();

        #pragma unroll
        for (int kk = 0; kk < KC; kk += 16) {
            unsigned a0 = *(const unsigned*)&Xs[r0 + grp    ][kk + qu * 2    ];
            unsigned a1 = *(const unsigned*)&Xs[r0 + grp + 8][kk + qu * 2    ];
            unsigned a2 = *(const unsigned*)&Xs[r0 + grp    ][kk + qu * 2 + 8];
            unsigned a3 = *(const unsigned*)&Xs[r0 + grp + 8][kk + qu * 2 + 8];
            #pragma unroll
            for (int nt = 0; nt < 8; nt++) {
                unsigned b0 = *(const unsigned*)&Wt[nt * 8 + grp][kk + qu * 2    ];
                unsigned b1 = *(const unsigned*)&Wt[nt * 8 + grp][kk + qu * 2 + 8];
                asm volatile(
                    "mma.sync.aligned.m16n8k16.row.col.f32.f16.f16.f32 "
                    "{%0,%1,%2,%3}, {%4,%5,%6,%7}, {%8,%9}, {%0,%1,%2,%3};"
                    : "+f"(d[nt][0]), "+f"(d[nt][1]), "+f"(d[nt][2]), "+f"(d[nt][3])
                    : "r"(a0), "r"(a1), "r"(a2), "r"(a3), "r"(b0), "r"(b1));
            }
        }
        __syncthreads();
    }

    int rA = n0 + r0 + grp;
    int rB = rA + 8;
    float diA = (rA < N) ? dinv[rA] : 0.0f;
    float diB = (rB < N) ? dinv[rB] : 0.0f;
    #pragma unroll
    for (int nt = 0; nt < 8; nt++) {
        if (rA < N)
            U[(size_t)rA * 32 + nt * 4 + qu] = __floats2half2_rn(d[nt][0] * diA, d[nt][1] * diA);
        if (rB < N)
            U[(size_t)rB * 32 + nt * 4 + qu] = __floats2half2_rn(d[nt][2] * diB, d[nt][3] * diB);
    }
}

// ---------------- CSR gather-aggregate (fp16 u, fp32 accum) ----------------
// HALF_OUT: write __half2 rows (stride 32); else fp32 rows (stride OUTD).
template <int OUTD, bool RELU, bool HALF_OUT>
__global__ void agg_kernel(const int* __restrict__ esrc, const int* __restrict__ off,
                           const __half2* __restrict__ u, const float* __restrict__ dinv,
                           const float* __restrict__ b, void* __restrict__ outv, int N) {
    int w = (blockIdx.x * blockDim.x + threadIdx.x) >> 5;
    if (w >= N) return;
    int lane = threadIdx.x & 31;
    int s0 = off[w], s1 = off[w + 1];
    const bool active = (2 * lane < OUTD);

    float2 acc = make_float2(0.f, 0.f);
    if (active) acc = __half22float2(u[(size_t)w * 32 + lane]);  // self-loop

    for (int base = s0; base < s1; base += 32) {
        int m = min(32, s1 - base);
        int myS = (lane < m) ? esrc[base + lane] : 0;
        int j = 0;
        for (; j + 3 < m; j += 4) {
            int sA = __shfl_sync(0xffffffffu, myS, j);
            int sB = __shfl_sync(0xffffffffu, myS, j + 1);
            int sC = __shfl_sync(0xffffffffu, myS, j + 2);
            int sD = __shfl_sync(0xffffffffu, myS, j + 3);
            if (active) {
                float2 fA = __half22float2(u[(size_t)sA * 32 + lane]);
                float2 fB = __half22float2(u[(size_t)sB * 32 + lane]);
                float2 fC = __half22float2(u[(size_t)sC * 32 + lane]);
                float2 fD = __half22float2(u[(size_t)sD * 32 + lane]);
                acc.x += (fA.x + fB.x) + (fC.x + fD.x);
                acc.y += (fA.y + fB.y) + (fC.y + fD.y);
            }
        }
        for (; j < m; j++) {
            int sA = __shfl_sync(0xffffffffu, myS, j);
            if (active) {
                float2 fA = __half22float2(u[(size_t)sA * 32 + lane]);
                acc.x += fA.x;
                acc.y += fA.y;
            }
        }
    }

    if (active) {
        float di = dinv[w];
        float r0 = acc.x * di + b[2 * lane];
        float r1 = acc.y * di + b[2 * lane + 1];
        if (RELU) { r0 = fmaxf(r0, 0.0f); r1 = fmaxf(r1, 0.0f); }
        if (HALF_OUT) {
            ((__half2*)outv)[(size_t)w * 32 + lane] = __floats2half2_rn(r0, r1);
        } else {
            *(float2*)((float*)outv + (size_t)w * OUTD + 2 * lane) = make_float2(r0, r1);
        }
    }
}

// ---------------- launch ----------------
extern "C" void kernel_launch(void* const* d_in, const int* in_sizes, int n_in,
                              void* d_out, int out_size) {
    const float* x    = (const float*)d_in[0];
    const void*  eidx = d_in[1];
    const float* W1   = (const float*)d_in[2];
    const float* b1   = (const float*)d_in[3];
    const float* W2   = (const float*)d_in[4];
    const float* b2   = (const float*)d_in[5];
    const float* W3   = (const float*)d_in[6];
    const float* b3   = (const float*)d_in[7];
    float* out = (float*)d_out;

    const int N = in_sizes[0] / D_IN;   // 100000
    const int E = in_sizes[1] / 2;      // 1600000

    __half2 *pu, *pact;
    float *pdinv, *pW3p;
    int *pcnt, *poff, *pcur, *pbsum, *pesrc;
    cudaGetSymbolAddress((void**)&pu,    g_u);
    cudaGetSymbolAddress((void**)&pact,  g_act);
    cudaGetSymbolAddress((void**)&pdinv, g_dinv);
    cudaGetSymbolAddress((void**)&pW3p,  g_W3p);
    cudaGetSymbolAddress((void**)&pcnt,  g_cnt);
    cudaGetSymbolAddress((void**)&poff,  g_off);
    cudaGetSymbolAddress((void**)&pcur,  g_cur);
    cudaGetSymbolAddress((void**)&pbsum, g_bsum);
    cudaGetSymbolAddress((void**)&pesrc, g_esrc);

    const int TB = 256;
    const int eb = (E + TB - 1) / TB;
    const int nb = (N + TB - 1) / TB;
    const int nscan = (N + 511) / 512;          // 196 (<=512 required by scanB)
    const int gemm_blocks = (N + 127) / 128;
    const int agg_blocks = (N + 7) / 8;

    // preprocessing (5 launches)
    init_kernel<<<nb, TB>>>((const unsigned*)eidx, pcnt, W3, pW3p, N);
    count_kernel<<<eb, TB>>>(eidx, pcnt, E);
    scanA_kernel<<<nscan, 512>>>(pcnt, poff, pbsum, N);
    scanB_kernel<<<nscan, 512>>>(poff, pbsum, pcur, pdinv, pcnt, N, E);
    bucket_kernel<<<eb, TB>>>(eidx, pcur, pesrc, E);

    // layer 1: 128 -> 64, relu (fp32 in, fp16 act out)
    gemm_mma_kernel<128, false><<<gemm_blocks, TB>>>(x, W1, pdinv, pu, N);
    agg_kernel<64, true, true><<<agg_blocks, TB>>>(pesrc, poff, pu, pdinv, b1, pact, N);

    // layer 2: 64 -> 64, relu (fp16 in/out)
    gemm_mma_kernel<64, true><<<gemm_blocks, TB>>>(pact, W2, pdinv, pu, N);
    agg_kernel<64, true, true><<<agg_blocks, TB>>>(pesrc, poff, pu, pdinv, b2, pact, N);

    // layer 3: 64 -> 40 (padded W; fp32 final out)
    gemm_mma_kernel<64, true><<<gemm_blocks, TB>>>(pact, pW3p, pdinv, pu, N);
    agg_kernel<40, false, false><<<agg_blocks, TB>>>(pesrc, poff, pu, pdinv, b3, out, N);
}